// round 1
// baseline (speedup 1.0000x reference)
#include <cuda_runtime.h>
#include <math.h>
#include <stdint.h>

// ---------------- problem constants ----------------
constexpr int Bn   = 4;
constexpr int FC   = 64;
constexpr int TC   = 64;
constexpr int HID  = 48;
constexpr int HR   = 2;
constexpr int Gg   = 8;
constexpr int Hh   = 128;
constexpr int Wd   = 256;
constexpr int Dd   = 2 * HR + 1;      // 5
constexpr int CG   = FC / Gg;          // 8
constexpr int GRU_IN = TC + 2 * FC + 4 + Gg * Dd;  // 236
constexpr int HW   = Hh * Wd;          // 32768

// output layout: d(4*HW) sx(4*HW) sy(4*HW) h_new(4*64*HW) conf(4*HW)
constexpr size_t O_D    = 0;
constexpr size_t O_SX   = (size_t)Bn * HW;
constexpr size_t O_SY   = 2 * (size_t)Bn * HW;
constexpr size_t O_H    = 3 * (size_t)Bn * HW;
constexpr size_t O_CONF = 3 * (size_t)Bn * HW + (size_t)Bn * TC * HW;

// ---------------- scratch (no allocations allowed) ----------------
__device__ float g_hctx [(size_t)Bn * GRU_IN * HW];  // feat|fL|fR_w|d,sx,sy,conf|cost
__device__ float g_zpre [(size_t)Bn * TC * HW];
__device__ float g_rfeat[(size_t)Bn * TC * HW];      // first r_pre, then sigmoid(r)*feat
__device__ float g_qpre [(size_t)Bn * TC * HW];
__device__ float g_ta   [(size_t)Bn * HID * HW];     // raw conv out
__device__ float g_tb   [(size_t)Bn * HID * HW];     // normalized + silu
__device__ float g_stats[Bn * Gg * 2];               // mean, rstd per (b,g)

// ---------------- helpers ----------------
__device__ __forceinline__ float sigmoidf_(float x) { return 1.f / (1.f + expf(-x)); }
__device__ __forceinline__ float softplusf_(float x) {
    return fmaxf(x, 0.f) + log1pf(expf(-fabsf(x)));
}

// ---------------- K1: sampling + cost volume + ctx assembly ----------------
__global__ void build_ctx_k(const float* __restrict__ d, const float* __restrict__ sx,
                            const float* __restrict__ sy, const float* __restrict__ conf,
                            const float* __restrict__ feat, const float* __restrict__ fL,
                            const float* __restrict__ fR) {
    int idx = blockIdx.x * blockDim.x + threadIdx.x;
    if (idx >= Bn * HW) return;
    int b = idx / HW;
    int p = idx - b * HW;
    int w = p & (Wd - 1);

    float d0 = d[(size_t)b * HW + p];

    int i0[Dd], i1[Dd];
    float w1[Dd];
#pragma unroll
    for (int j = 0; j < Dd; j++) {
        float x = (float)w - d0 - (float)(j - HR);
        x = fminf(fmaxf(x, 0.f), (float)(Wd - 1));
        float x0 = floorf(x);
        w1[j] = x - x0;
        i0[j] = (int)x0;
        i1[j] = min(i0[j] + 1, Wd - 1);
    }

    float* hb = g_hctx + (size_t)b * GRU_IN * HW;
    const float* fRrow = fR + (size_t)b * FC * HW + (size_t)(p - w); // start of row h
    const float* fLp   = fL + (size_t)b * FC * HW + p;
    const float* ftp   = feat + (size_t)b * FC * HW + p;

    float cost[Dd] = {0.f, 0.f, 0.f, 0.f, 0.f};
    for (int c = 0; c < FC; c++) {
        const float* row = fRrow + (size_t)c * HW;
        float fl = fLp[(size_t)c * HW];
        hb[(size_t)c * HW + p]        = ftp[(size_t)c * HW];   // feat
        hb[(size_t)(FC + c) * HW + p] = fl;                    // fL
#pragma unroll
        for (int j = 0; j < Dd; j++) {
            float s = row[i0[j]] * (1.f - w1[j]) + row[i1[j]] * w1[j];
            cost[j] += fl * s;
            if (j == HR) hb[(size_t)(2 * FC + c) * HW + p] = s;  // fR_w
        }
        if ((c & (CG - 1)) == CG - 1) {
            int g = c >> 3;
#pragma unroll
            for (int j = 0; j < Dd; j++) {
                hb[(size_t)(3 * FC + 4 + g * Dd + j) * HW + p] = cost[j] * (1.f / (float)CG);
                cost[j] = 0.f;
            }
        }
    }
    hb[(size_t)(3 * FC + 0) * HW + p] = d0;
    hb[(size_t)(3 * FC + 1) * HW + p] = sx[(size_t)b * HW + p];
    hb[(size_t)(3 * FC + 2) * HW + p] = sy[(size_t)b * HW + p];
    hb[(size_t)(3 * FC + 3) * HW + p] = conf[(size_t)b * HW + p];
}

// ---------------- generic direct 3x3 conv ----------------
// Tile: 16x16 pixels, each thread computes 4 consecutive x-pixels * 16 out channels.
// Input is a virtual concat of [head (c_head ch)] + [rest].
template <int COUT>
__global__ __launch_bounds__(256)
void conv3x3_k(const float* __restrict__ in_head, int head_cs, int c_head,
               const float* __restrict__ in_rest, int rest_cs,
               int c_total,
               const float* __restrict__ wgt, const float* __restrict__ bias,
               float* __restrict__ out, int out_cs) {
    constexpr int OCG = COUT / 16;     // oc groups
    constexpr int NT  = 64 * OCG;      // threads
    constexpr int ICCH = 4;

    __shared__ __align__(16) float s_in[ICCH][18 * 18];
    __shared__ __align__(16) float s_w[ICCH][9][COUT];

    const int tid  = threadIdx.x;
    const int ocg  = tid % OCG;
    const int slot = tid / OCG;        // 0..63
    const int row  = slot >> 2;        // 0..15
    const int x0   = (slot & 3) * 4;   // 0,4,8,12

    const int b   = blockIdx.z;
    const int ty0 = blockIdx.y * 16;
    const int tx0 = blockIdx.x * 16;

    float acc[16][4];
#pragma unroll
    for (int k = 0; k < 16; k++)
#pragma unroll
        for (int px = 0; px < 4; px++) acc[k][px] = 0.f;

    for (int ic0 = 0; ic0 < c_total; ic0 += ICCH) {
        const int nc = min(ICCH, c_total - ic0);
        // load input patch (with halo, zero padded)
        for (int i = tid; i < nc * 324; i += NT) {
            int c = i / 324;
            int pp = i - c * 324;
            int py = pp / 18, px = pp - py * 18;
            int gy = ty0 + py - 1, gx = tx0 + px - 1;
            int cc = ic0 + c;
            float v = 0.f;
            if (gy >= 0 && gy < Hh && gx >= 0 && gx < Wd) {
                const float* ptr = (cc < c_head)
                    ? in_head + ((size_t)b * head_cs + cc) * HW
                    : in_rest + ((size_t)b * rest_cs + (cc - c_head)) * HW;
                v = ptr[gy * Wd + gx];
            }
            s_in[c][pp] = v;
        }
        // load weights: s_w[c][tap][oc]
        for (int i = tid; i < nc * 9 * COUT; i += NT) {
            int c = i / (9 * COUT);
            int r = i - c * (9 * COUT);
            int tap = r / COUT;
            int oc  = r - tap * COUT;
            s_w[c][tap][oc] = wgt[((size_t)oc * c_total + ic0 + c) * 9 + tap];
        }
        __syncthreads();

        for (int c = 0; c < nc; c++) {
            float v[3][6];
#pragma unroll
            for (int dy = 0; dy < 3; dy++)
#pragma unroll
                for (int dx = 0; dx < 6; dx++)
                    v[dy][dx] = s_in[c][(row + dy) * 18 + x0 + dx];
#pragma unroll
            for (int tap = 0; tap < 9; tap++) {
                const int tdy = tap / 3, tdx = tap - tdy * 3;
                float wv[16];
                const float4* wp = reinterpret_cast<const float4*>(&s_w[c][tap][ocg * 16]);
#pragma unroll
                for (int q = 0; q < 4; q++) {
                    float4 t = wp[q];
                    wv[4 * q] = t.x; wv[4 * q + 1] = t.y; wv[4 * q + 2] = t.z; wv[4 * q + 3] = t.w;
                }
#pragma unroll
                for (int k = 0; k < 16; k++)
#pragma unroll
                    for (int px = 0; px < 4; px++)
                        acc[k][px] += v[tdy][px + tdx] * wv[k];
            }
        }
        __syncthreads();
    }

    const int gy = ty0 + row;
    const int gx = tx0 + x0;
#pragma unroll
    for (int k = 0; k < 16; k++) {
        int oc = ocg * 16 + k;
        float bv = bias ? bias[oc] : 0.f;
        float4 r = make_float4(acc[k][0] + bv, acc[k][1] + bv, acc[k][2] + bv, acc[k][3] + bv);
        *reinterpret_cast<float4*>(out + ((size_t)b * out_cs + oc) * HW + gy * Wd + gx) = r;
    }
}

// ---------------- GRU elementwise ----------------
__global__ void gru_rfeat_k(const float* __restrict__ feat) {
    size_t i = (size_t)blockIdx.x * blockDim.x + threadIdx.x;
    if (i >= (size_t)Bn * TC * HW) return;
    g_rfeat[i] = sigmoidf_(g_rfeat[i]) * feat[i];
}

__global__ void gru_combine_k(const float* __restrict__ feat, float* __restrict__ out_h) {
    size_t i = (size_t)blockIdx.x * blockDim.x + threadIdx.x;
    if (i >= (size_t)Bn * TC * HW) return;
    float z = sigmoidf_(g_zpre[i]);
    float q = tanhf(g_qpre[i]);
    out_h[i] = (1.f - z) * feat[i] + z * q;
}

// ---------------- group norm ----------------
__global__ void gn_stats_k(const float* __restrict__ x) {
    const int bg = blockIdx.x;          // b*8+g
    const int b = bg >> 3, g = bg & 7;
    const float* base = x + ((size_t)b * HID + g * (HID / Gg)) * HW;
    const int n = (HID / Gg) * HW;      // 196608
    float s = 0.f, s2 = 0.f;
    for (int i = threadIdx.x; i < n; i += blockDim.x) {
        float v = base[i];
        s += v; s2 += v * v;
    }
    __shared__ float sh[512];
    sh[threadIdx.x] = s;
    sh[256 + threadIdx.x] = s2;
    __syncthreads();
    for (int o = 128; o > 0; o >>= 1) {
        if (threadIdx.x < o) {
            sh[threadIdx.x] += sh[threadIdx.x + o];
            sh[256 + threadIdx.x] += sh[256 + threadIdx.x + o];
        }
        __syncthreads();
    }
    if (threadIdx.x == 0) {
        float m = sh[0] / (float)n;
        float var = sh[256] / (float)n - m * m;
        g_stats[bg * 2]     = m;
        g_stats[bg * 2 + 1] = rsqrtf(var + 1e-5f);
    }
}

__global__ void gn_apply_silu_k(const float* __restrict__ x,
                                const float* __restrict__ scale, const float* __restrict__ bias,
                                float* __restrict__ y) {
    size_t i = (size_t)blockIdx.x * blockDim.x + threadIdx.x;
    if (i >= (size_t)Bn * HID * HW) return;
    int c = (int)((i / HW) % HID);
    int b = (int)(i / ((size_t)HID * HW));
    int g = c / (HID / Gg);
    float m = g_stats[(b * Gg + g) * 2];
    float r = g_stats[(b * Gg + g) * 2 + 1];
    float v = (x[i] - m) * r * scale[c] + bias[c];
    y[i] = v * sigmoidf_(v);
}

// ---------------- heads (1x1 convs + activations) ----------------
__global__ void heads_k(const float* __restrict__ t,
                        const float* __restrict__ d, const float* __restrict__ sx,
                        const float* __restrict__ sy, const float* __restrict__ conf,
                        const float* __restrict__ wd, const float* __restrict__ bd,
                        const float* __restrict__ wsx, const float* __restrict__ bsx,
                        const float* __restrict__ wsy, const float* __restrict__ bsy,
                        const float* __restrict__ wc, const float* __restrict__ bc,
                        float* __restrict__ out) {
    int idx = blockIdx.x * blockDim.x + threadIdx.x;
    if (idx >= Bn * HW) return;
    int b = idx / HW;
    int p = idx - b * HW;
    const float* tb = t + (size_t)b * HID * HW + p;
    float ad = 0.f, asx = 0.f, asy = 0.f, ac = 0.f;
#pragma unroll
    for (int c = 0; c < HID; c++) {
        float v = tb[(size_t)c * HW];
        ad  += v * __ldg(&wd[c]);
        asx += v * __ldg(&wsx[c]);
        asy += v * __ldg(&wsy[c]);
        ac  += v * __ldg(&wc[c]);
    }
    float dv = d[idx];
    out[O_D + idx]    = softplusf_(ad + bd[0] + dv);
    out[O_SX + idx]   = sx[idx] + (asx + bsx[0]) * 0.1f;
    out[O_SY + idx]   = sy[idx] + (asy + bsy[0]) * 0.1f;
    out[O_CONF + idx] = sigmoidf_(ac + bc[0] + 2.f * conf[idx] - 1.f);
}

// ---------------- launch ----------------
extern "C" void kernel_launch(void* const* d_in, const int* in_sizes, int n_in,
                              void* d_out, int out_size) {
    const float* d      = (const float*)d_in[0];
    const float* sx     = (const float*)d_in[1];
    const float* sy     = (const float*)d_in[2];
    const float* conf   = (const float*)d_in[3];
    const float* feat   = (const float*)d_in[4];
    const float* fL     = (const float*)d_in[5];
    const float* fR     = (const float*)d_in[6];
    const float* conv_z_w = (const float*)d_in[7];
    const float* conv_z_b = (const float*)d_in[8];
    const float* conv_r_w = (const float*)d_in[9];
    const float* conv_r_b = (const float*)d_in[10];
    const float* conv_q_w = (const float*)d_in[11];
    const float* conv_q_b = (const float*)d_in[12];
    const float* trunk1_w = (const float*)d_in[13];
    const float* gn1_s    = (const float*)d_in[14];
    const float* gn1_b    = (const float*)d_in[15];
    const float* trunk2_w = (const float*)d_in[16];
    const float* gn2_s    = (const float*)d_in[17];
    const float* gn2_b    = (const float*)d_in[18];
    const float* head_d_w    = (const float*)d_in[19];
    const float* head_d_b    = (const float*)d_in[20];
    const float* head_sx_w   = (const float*)d_in[21];
    const float* head_sx_b   = (const float*)d_in[22];
    const float* head_sy_w   = (const float*)d_in[23];
    const float* head_sy_b   = (const float*)d_in[24];
    const float* head_conf_w = (const float*)d_in[25];
    const float* head_conf_b = (const float*)d_in[26];

    float* out = (float*)d_out;

    float *hctx, *zpre, *rfeat, *qpre, *ta, *tb;
    cudaGetSymbolAddress((void**)&hctx,  g_hctx);
    cudaGetSymbolAddress((void**)&zpre,  g_zpre);
    cudaGetSymbolAddress((void**)&rfeat, g_rfeat);
    cudaGetSymbolAddress((void**)&qpre,  g_qpre);
    cudaGetSymbolAddress((void**)&ta,    g_ta);
    cudaGetSymbolAddress((void**)&tb,    g_tb);

    float* h_new = out + O_H;

    // K1: ctx / cost volume
    build_ctx_k<<<(Bn * HW + 255) / 256, 256>>>(d, sx, sy, conf, feat, fL, fR);

    dim3 cgrid(Wd / 16, Hh / 16, Bn);

    // z and r convolutions over hctx (236 ch)
    conv3x3_k<TC><<<cgrid, 256>>>(hctx, GRU_IN, GRU_IN, nullptr, 0, GRU_IN,
                                  conv_z_w, conv_z_b, zpre, TC);
    conv3x3_k<TC><<<cgrid, 256>>>(hctx, GRU_IN, GRU_IN, nullptr, 0, GRU_IN,
                                  conv_r_w, conv_r_b, rfeat, TC);

    // r -> sigmoid(r)*feat
    {
        size_t n = (size_t)Bn * TC * HW;
        gru_rfeat_k<<<(unsigned)((n + 255) / 256), 256>>>(feat);
    }

    // q convolution: [rfeat(64) | hctx ch 64..235]
    conv3x3_k<TC><<<cgrid, 256>>>(rfeat, TC, TC, hctx + (size_t)TC * HW, GRU_IN, GRU_IN,
                                  conv_q_w, conv_q_b, qpre, TC);

    // GRU combine -> h_new (written straight into output buffer)
    {
        size_t n = (size_t)Bn * TC * HW;
        gru_combine_k<<<(unsigned)((n + 255) / 256), 256>>>(feat, h_new);
    }

    // trunk1: 64 -> 48, no bias
    conv3x3_k<HID><<<cgrid, 192>>>(h_new, TC, TC, nullptr, 0, TC,
                                   trunk1_w, nullptr, ta, HID);
    gn_stats_k<<<Bn * Gg, 256>>>(ta);
    {
        size_t n = (size_t)Bn * HID * HW;
        gn_apply_silu_k<<<(unsigned)((n + 255) / 256), 256>>>(ta, gn1_s, gn1_b, tb);
    }

    // trunk2: 48 -> 48, no bias
    conv3x3_k<HID><<<cgrid, 192>>>(tb, HID, HID, nullptr, 0, HID,
                                   trunk2_w, nullptr, ta, HID);
    gn_stats_k<<<Bn * Gg, 256>>>(ta);
    {
        size_t n = (size_t)Bn * HID * HW;
        gn_apply_silu_k<<<(unsigned)((n + 255) / 256), 256>>>(ta, gn2_s, gn2_b, tb);
    }

    // heads
    heads_k<<<(Bn * HW + 255) / 256, 256>>>(tb, d, sx, sy, conf,
                                            head_d_w, head_d_b, head_sx_w, head_sx_b,
                                            head_sy_w, head_sy_b, head_conf_w, head_conf_b,
                                            out);
}

// round 10
// speedup vs baseline: 1.8152x; 1.8152x over previous
#include <cuda_runtime.h>
#include <math.h>
#include <stdint.h>

// ---------------- problem constants ----------------
constexpr int Bn   = 4;
constexpr int FC   = 64;
constexpr int TC   = 64;
constexpr int HID  = 48;
constexpr int HR   = 2;
constexpr int Gg   = 8;
constexpr int Hh   = 128;
constexpr int Wd   = 256;
constexpr int Dd   = 2 * HR + 1;      // 5
constexpr int CG   = FC / Gg;          // 8
constexpr int GRU_IN = TC + 2 * FC + 4 + Gg * Dd;  // 236
constexpr int HW   = Hh * Wd;          // 32768

// output layout: d(4*HW) sx(4*HW) sy(4*HW) h_new(4*64*HW) conf(4*HW)
constexpr size_t O_D    = 0;
constexpr size_t O_SX   = (size_t)Bn * HW;
constexpr size_t O_SY   = 2 * (size_t)Bn * HW;
constexpr size_t O_H    = 3 * (size_t)Bn * HW;
constexpr size_t O_CONF = 3 * (size_t)Bn * HW + (size_t)Bn * TC * HW;

// ---------------- scratch (no allocations allowed) ----------------
__device__ float g_hctx [(size_t)Bn * GRU_IN * HW];  // feat|fL|fR_w|d,sx,sy,conf|cost
__device__ float g_zpre [(size_t)Bn * TC * HW];
__device__ float g_rfeat[(size_t)Bn * TC * HW];
__device__ float g_qpre [(size_t)Bn * TC * HW];
__device__ float g_ta   [(size_t)Bn * HID * HW];
__device__ float g_tb   [(size_t)Bn * HID * HW];
__device__ float g_stats[Bn * Gg * 2];

// prepacked weights (tf32 bits): [chunk][tap][k=32][n=64]
constexpr int NCH_GRU = (GRU_IN + 31) / 32;   // 8
constexpr int NCH_T1  = (TC + 31) / 32;       // 2
constexpr int NCH_T2  = (HID + 31) / 32;      // 2
__device__ float g_wz [(size_t)NCH_GRU * 9 * 32 * 64];
__device__ float g_wr [(size_t)NCH_GRU * 9 * 32 * 64];
__device__ float g_wq [(size_t)NCH_GRU * 9 * 32 * 64];
__device__ float g_wt1[(size_t)NCH_T1  * 9 * 32 * 64];
__device__ float g_wt2[(size_t)NCH_T2  * 9 * 32 * 64];

// ---------------- helpers ----------------
__device__ __forceinline__ float sigmoidf_(float x) { return 1.f / (1.f + expf(-x)); }
__device__ __forceinline__ float softplusf_(float x) {
    return fmaxf(x, 0.f) + log1pf(expf(-fabsf(x)));
}
__device__ __forceinline__ uint32_t f2tf32(float f) {
    uint32_t o;
    asm("cvt.rna.tf32.f32 %0, %1;" : "=r"(o) : "f"(f));
    return o;
}

// ---------------- K1: sampling + cost volume + ctx assembly ----------------
__global__ void build_ctx_k(const float* __restrict__ d, const float* __restrict__ sx,
                            const float* __restrict__ sy, const float* __restrict__ conf,
                            const float* __restrict__ feat, const float* __restrict__ fL,
                            const float* __restrict__ fR) {
    int idx = blockIdx.x * blockDim.x + threadIdx.x;
    if (idx >= Bn * HW) return;
    int b = idx / HW;
    int p = idx - b * HW;
    int w = p & (Wd - 1);

    float d0 = d[(size_t)b * HW + p];

    int i0[Dd], i1[Dd];
    float w1[Dd];
#pragma unroll
    for (int j = 0; j < Dd; j++) {
        float x = (float)w - d0 - (float)(j - HR);
        x = fminf(fmaxf(x, 0.f), (float)(Wd - 1));
        float x0 = floorf(x);
        w1[j] = x - x0;
        i0[j] = (int)x0;
        i1[j] = min(i0[j] + 1, Wd - 1);
    }

    float* hb = g_hctx + (size_t)b * GRU_IN * HW;
    const float* fRrow = fR + (size_t)b * FC * HW + (size_t)(p - w);
    const float* fLp   = fL + (size_t)b * FC * HW + p;
    const float* ftp   = feat + (size_t)b * FC * HW + p;

    float cost[Dd] = {0.f, 0.f, 0.f, 0.f, 0.f};
    for (int c = 0; c < FC; c++) {
        const float* row = fRrow + (size_t)c * HW;
        float fl = fLp[(size_t)c * HW];
        hb[(size_t)c * HW + p]        = ftp[(size_t)c * HW];
        hb[(size_t)(FC + c) * HW + p] = fl;
#pragma unroll
        for (int j = 0; j < Dd; j++) {
            float s = row[i0[j]] * (1.f - w1[j]) + row[i1[j]] * w1[j];
            cost[j] += fl * s;
            if (j == HR) hb[(size_t)(2 * FC + c) * HW + p] = s;
        }
        if ((c & (CG - 1)) == CG - 1) {
            int g = c >> 3;
#pragma unroll
            for (int j = 0; j < Dd; j++) {
                hb[(size_t)(3 * FC + 4 + g * Dd + j) * HW + p] = cost[j] * (1.f / (float)CG);
                cost[j] = 0.f;
            }
        }
    }
    hb[(size_t)(3 * FC + 0) * HW + p] = d0;
    hb[(size_t)(3 * FC + 1) * HW + p] = sx[(size_t)b * HW + p];
    hb[(size_t)(3 * FC + 2) * HW + p] = sy[(size_t)b * HW + p];
    hb[(size_t)(3 * FC + 3) * HW + p] = conf[(size_t)b * HW + p];
}

// ---------------- weight prepack (tf32) ----------------
// dst[chunk][tap][k=32][n=64]: n = out channel (zero-padded to 64), k = in-channel within chunk
__global__ void prepack_mma_k(const float* __restrict__ w, float* __restrict__ dst,
                              int c_total, int cout, int nchunks) {
    int total = nchunks * 9 * 32 * 64;
    int i = blockIdx.x * blockDim.x + threadIdx.x;
    if (i >= total) return;
    int n   = i & 63;
    int k   = (i >> 6) & 31;
    int tap = (i >> 11) % 9;
    int ch  = i / (2048 * 9);
    int c = ch * 32 + k;
    float v = (c < c_total && n < cout) ? w[((size_t)n * c_total + c) * 9 + tap] : 0.f;
    dst[i] = __uint_as_float(f2tf32(v));
}

// ---------------- mma.sync tf32 implicit-GEMM 3x3 conv ----------------
// CTA = one (b,y) image row: M=256 px, N=64 (COUT padded), K = nchunks*32 per tap.
// 8 warps: warpM = wid&3 (64 px each), warpN = wid>>2 (32 ch each).
// smem: A row tile [32][264] (tf32 bits, halo'd), B taps [3][32][72] (tf32 bits).
constexpr int SA_PITCH = 264;   // 264 % 32 == 8 -> conflict-free frag loads
constexpr int SB_PITCH = 72;    // 72 % 32 == 8
constexpr int CONV_SMEM = (32 * SA_PITCH + 3 * 32 * SB_PITCH) * 4;  // 61440 B

template <int COUT>
__global__ __launch_bounds__(256, 2)
void conv3x3_mma_k(const float* __restrict__ Ahead, int head_bstride, int c_head,
                   const float* __restrict__ Arest, int rest_bstride,
                   int c_total, int nchunks,
                   const float* __restrict__ wpack, const float* __restrict__ bias,
                   float* __restrict__ out) {
    extern __shared__ float smem[];
    float* sA = smem;                       // [32][SA_PITCH]
    float* sB = smem + 32 * SA_PITCH;       // [3][32][SB_PITCH]

    const int tid  = threadIdx.x;
    const int wid  = tid >> 5;
    const int lane = tid & 31;
    const int gid  = lane >> 2;   // 0..7
    const int tig  = lane & 3;    // 0..3
    const int warpM = wid & 3;    // 0..3
    const int warpN = wid >> 2;   // 0..1

    const int y = blockIdx.x;
    const int b = blockIdx.y;

    const float* pa_b = Ahead + (size_t)b * head_bstride * HW;
    const float* pr_b = Arest + (size_t)b * rest_bstride * HW;

    float acc[4][4][4];
#pragma unroll
    for (int mf = 0; mf < 4; mf++)
#pragma unroll
        for (int nf = 0; nf < 4; nf++)
#pragma unroll
            for (int r = 0; r < 4; r++) acc[mf][nf][r] = 0.f;

    for (int chunk = 0; chunk < nchunks; ++chunk) {
        for (int dy = 0; dy < 3; ++dy) {
            const int yy = y + dy - 1;
            __syncthreads();   // previous iteration's reads done

            // ---- fill A: 32 channels x 264 (x = gx+1, halo zeros), tf32 bits ----
            {
                const bool rowok = (yy >= 0) && (yy < Hh);
                for (int c = 0; c < 32; ++c) {
                    const int cg = chunk * 32 + c;
                    const float* src = nullptr;
                    if (rowok && cg < c_total)
                        src = (cg < c_head ? pa_b + (size_t)cg * HW
                                           : pr_b + (size_t)(cg - c_head) * HW)
                              + (size_t)yy * Wd;
                    float* dstrow = sA + c * SA_PITCH;
                    for (int xi = tid; xi < SA_PITCH; xi += 256) {
                        int gx = xi - 1;
                        float v = 0.f;
                        if (src && gx >= 0 && gx < Wd) v = src[gx];
                        dstrow[xi] = __uint_as_float(f2tf32(v));
                    }
                }
            }
            // ---- fill B: taps dy*3+0..2, each [32][64] -> pitch 72 ----
            {
                const float* wsrc = wpack + ((size_t)chunk * 9 + dy * 3) * (32 * 64);
                for (int i = tid; i < 3 * 32 * 64; i += 256) {
                    int t = i >> 11;          // /2048
                    int k = (i >> 6) & 31;
                    int n = i & 63;
                    sB[(t * 32 + k) * SB_PITCH + n] = wsrc[i];
                }
            }
            __syncthreads();

            // ---- compute: 3 dx taps x 4 ksteps ----
            for (int dx = 0; dx < 3; ++dx) {
                const float* sBt = sB + dx * 32 * SB_PITCH;
                const int x0 = warpM * 64 + gid + dx;   // xi index of output px (m) + dx
#pragma unroll
                for (int ks = 0; ks < 4; ++ks) {
                    const int k0 = ks * 8 + tig;
                    uint32_t bf[4][2];
#pragma unroll
                    for (int nf = 0; nf < 4; ++nf) {
                        const int n0 = warpN * 32 + nf * 8 + gid;
                        bf[nf][0] = __float_as_uint(sBt[k0 * SB_PITCH + n0]);
                        bf[nf][1] = __float_as_uint(sBt[(k0 + 4) * SB_PITCH + n0]);
                    }
                    uint32_t af[4][4];
#pragma unroll
                    for (int mf = 0; mf < 4; ++mf) {
                        const int xm = x0 + mf * 16;
                        af[mf][0] = __float_as_uint(sA[k0 * SA_PITCH + xm]);
                        af[mf][1] = __float_as_uint(sA[k0 * SA_PITCH + xm + 8]);
                        af[mf][2] = __float_as_uint(sA[(k0 + 4) * SA_PITCH + xm]);
                        af[mf][3] = __float_as_uint(sA[(k0 + 4) * SA_PITCH + xm + 8]);
                    }
#pragma unroll
                    for (int mf = 0; mf < 4; ++mf)
#pragma unroll
                        for (int nf = 0; nf < 4; ++nf)
                            asm volatile(
                                "mma.sync.aligned.m16n8k8.row.col.f32.tf32.tf32.f32 "
                                "{%0,%1,%2,%3}, {%4,%5,%6,%7}, {%8,%9}, {%0,%1,%2,%3};"
                                : "+f"(acc[mf][nf][0]), "+f"(acc[mf][nf][1]),
                                  "+f"(acc[mf][nf][2]), "+f"(acc[mf][nf][3])
                                : "r"(af[mf][0]), "r"(af[mf][1]),
                                  "r"(af[mf][2]), "r"(af[mf][3]),
                                  "r"(bf[nf][0]), "r"(bf[nf][1]));
                }
            }
        }
    }

    // ---- epilogue ----
    float* ob = out + (size_t)b * COUT * HW + (size_t)y * Wd;
#pragma unroll
    for (int mf = 0; mf < 4; ++mf) {
        const int m0 = warpM * 64 + mf * 16 + gid;
#pragma unroll
        for (int nf = 0; nf < 4; ++nf) {
            const int n0 = warpN * 32 + nf * 8 + 2 * tig;
#pragma unroll
            for (int r = 0; r < 4; ++r) {
                const int n = n0 + (r & 1);
                const int m = m0 + ((r >> 1) ? 8 : 0);
                if (n < COUT) {
                    float v = acc[mf][nf][r];
                    if (bias) v += bias[n];
                    ob[(size_t)n * HW + m] = v;
                }
            }
        }
    }
}

// ---------------- GRU elementwise ----------------
__global__ void gru_rfeat_k(const float* __restrict__ feat) {
    size_t i = (size_t)blockIdx.x * blockDim.x + threadIdx.x;
    if (i >= (size_t)Bn * TC * HW) return;
    g_rfeat[i] = sigmoidf_(g_rfeat[i]) * feat[i];
}

__global__ void gru_combine_k(const float* __restrict__ feat, float* __restrict__ out_h) {
    size_t i = (size_t)blockIdx.x * blockDim.x + threadIdx.x;
    if (i >= (size_t)Bn * TC * HW) return;
    float z = sigmoidf_(g_zpre[i]);
    float q = tanhf(g_qpre[i]);
    out_h[i] = (1.f - z) * feat[i] + z * q;
}

// ---------------- group norm ----------------
__global__ void gn_stats_k(const float* __restrict__ x) {
    const int bg = blockIdx.x;
    const int b = bg >> 3, g = bg & 7;
    const float* base = x + ((size_t)b * HID + g * (HID / Gg)) * HW;
    const int n = (HID / Gg) * HW;
    float s = 0.f, s2 = 0.f;
    for (int i = threadIdx.x; i < n; i += blockDim.x) {
        float v = base[i];
        s += v; s2 += v * v;
    }
    __shared__ float sh[512];
    sh[threadIdx.x] = s;
    sh[256 + threadIdx.x] = s2;
    __syncthreads();
    for (int o = 128; o > 0; o >>= 1) {
        if (threadIdx.x < o) {
            sh[threadIdx.x] += sh[threadIdx.x + o];
            sh[256 + threadIdx.x] += sh[256 + threadIdx.x + o];
        }
        __syncthreads();
    }
    if (threadIdx.x == 0) {
        float m = sh[0] / (float)n;
        float var = sh[256] / (float)n - m * m;
        g_stats[bg * 2]     = m;
        g_stats[bg * 2 + 1] = rsqrtf(var + 1e-5f);
    }
}

__global__ void gn_apply_silu_k(const float* __restrict__ x,
                                const float* __restrict__ scale, const float* __restrict__ bias,
                                float* __restrict__ y) {
    size_t i = (size_t)blockIdx.x * blockDim.x + threadIdx.x;
    if (i >= (size_t)Bn * HID * HW) return;
    int c = (int)((i / HW) % HID);
    int b = (int)(i / ((size_t)HID * HW));
    int g = c / (HID / Gg);
    float m = g_stats[(b * Gg + g) * 2];
    float r = g_stats[(b * Gg + g) * 2 + 1];
    float v = (x[i] - m) * r * scale[c] + bias[c];
    y[i] = v * sigmoidf_(v);
}

// ---------------- heads ----------------
__global__ void heads_k(const float* __restrict__ t,
                        const float* __restrict__ d, const float* __restrict__ sx,
                        const float* __restrict__ sy, const float* __restrict__ conf,
                        const float* __restrict__ wd, const float* __restrict__ bd,
                        const float* __restrict__ wsx, const float* __restrict__ bsx,
                        const float* __restrict__ wsy, const float* __restrict__ bsy,
                        const float* __restrict__ wc, const float* __restrict__ bc,
                        float* __restrict__ out) {
    int idx = blockIdx.x * blockDim.x + threadIdx.x;
    if (idx >= Bn * HW) return;
    int b = idx / HW;
    int p = idx - b * HW;
    const float* tb = t + (size_t)b * HID * HW + p;
    float ad = 0.f, asx = 0.f, asy = 0.f, ac = 0.f;
#pragma unroll
    for (int c = 0; c < HID; c++) {
        float v = tb[(size_t)c * HW];
        ad  += v * __ldg(&wd[c]);
        asx += v * __ldg(&wsx[c]);
        asy += v * __ldg(&wsy[c]);
        ac  += v * __ldg(&wc[c]);
    }
    float dv = d[idx];
    out[O_D + idx]    = softplusf_(ad + bd[0] + dv);
    out[O_SX + idx]   = sx[idx] + (asx + bsx[0]) * 0.1f;
    out[O_SY + idx]   = sy[idx] + (asy + bsy[0]) * 0.1f;
    out[O_CONF + idx] = sigmoidf_(ac + bc[0] + 2.f * conf[idx] - 1.f);
}

// ---------------- launch ----------------
extern "C" void kernel_launch(void* const* d_in, const int* in_sizes, int n_in,
                              void* d_out, int out_size) {
    const float* d      = (const float*)d_in[0];
    const float* sx     = (const float*)d_in[1];
    const float* sy     = (const float*)d_in[2];
    const float* conf   = (const float*)d_in[3];
    const float* feat   = (const float*)d_in[4];
    const float* fL     = (const float*)d_in[5];
    const float* fR     = (const float*)d_in[6];
    const float* conv_z_w = (const float*)d_in[7];
    const float* conv_z_b = (const float*)d_in[8];
    const float* conv_r_w = (const float*)d_in[9];
    const float* conv_r_b = (const float*)d_in[10];
    const float* conv_q_w = (const float*)d_in[11];
    const float* conv_q_b = (const float*)d_in[12];
    const float* trunk1_w = (const float*)d_in[13];
    const float* gn1_s    = (const float*)d_in[14];
    const float* gn1_b    = (const float*)d_in[15];
    const float* trunk2_w = (const float*)d_in[16];
    const float* gn2_s    = (const float*)d_in[17];
    const float* gn2_b    = (const float*)d_in[18];
    const float* head_d_w    = (const float*)d_in[19];
    const float* head_d_b    = (const float*)d_in[20];
    const float* head_sx_w   = (const float*)d_in[21];
    const float* head_sx_b   = (const float*)d_in[22];
    const float* head_sy_w   = (const float*)d_in[23];
    const float* head_sy_b   = (const float*)d_in[24];
    const float* head_conf_w = (const float*)d_in[25];
    const float* head_conf_b = (const float*)d_in[26];

    float* out = (float*)d_out;

    float *hctx, *zpre, *rfeat, *qpre, *ta, *tb;
    float *wz, *wr, *wq, *wt1, *wt2;
    cudaGetSymbolAddress((void**)&hctx,  g_hctx);
    cudaGetSymbolAddress((void**)&zpre,  g_zpre);
    cudaGetSymbolAddress((void**)&rfeat, g_rfeat);
    cudaGetSymbolAddress((void**)&qpre,  g_qpre);
    cudaGetSymbolAddress((void**)&ta,    g_ta);
    cudaGetSymbolAddress((void**)&tb,    g_tb);
    cudaGetSymbolAddress((void**)&wz,    g_wz);
    cudaGetSymbolAddress((void**)&wr,    g_wr);
    cudaGetSymbolAddress((void**)&wq,    g_wq);
    cudaGetSymbolAddress((void**)&wt1,   g_wt1);
    cudaGetSymbolAddress((void**)&wt2,   g_wt2);

    float* h_new = out + O_H;

    // dynamic smem opt-in (idempotent)
    cudaFuncSetAttribute(conv3x3_mma_k<TC>,  cudaFuncAttributeMaxDynamicSharedMemorySize, CONV_SMEM);
    cudaFuncSetAttribute(conv3x3_mma_k<HID>, cudaFuncAttributeMaxDynamicSharedMemorySize, CONV_SMEM);

    // K1: ctx / cost volume
    build_ctx_k<<<(Bn * HW + 255) / 256, 256>>>(d, sx, sy, conf, feat, fL, fR);

    // weight prepack (idempotent each call)
    {
        int n = NCH_GRU * 9 * 32 * 64;
        prepack_mma_k<<<(n + 255) / 256, 256>>>(conv_z_w, wz, GRU_IN, TC, NCH_GRU);
        prepack_mma_k<<<(n + 255) / 256, 256>>>(conv_r_w, wr, GRU_IN, TC, NCH_GRU);
        prepack_mma_k<<<(n + 255) / 256, 256>>>(conv_q_w, wq, GRU_IN, TC, NCH_GRU);
        int n1 = NCH_T1 * 9 * 32 * 64;
        prepack_mma_k<<<(n1 + 255) / 256, 256>>>(trunk1_w, wt1, TC, HID, NCH_T1);
        int n2 = NCH_T2 * 9 * 32 * 64;
        prepack_mma_k<<<(n2 + 255) / 256, 256>>>(trunk2_w, wt2, HID, HID, NCH_T2);
    }

    dim3 cgrid(Hh, Bn);

    // z and r convolutions over hctx (236 ch)
    conv3x3_mma_k<TC><<<cgrid, 256, CONV_SMEM>>>(hctx, GRU_IN, GRU_IN, hctx, GRU_IN,
                                                 GRU_IN, NCH_GRU, wz, conv_z_b, zpre);
    conv3x3_mma_k<TC><<<cgrid, 256, CONV_SMEM>>>(hctx, GRU_IN, GRU_IN, hctx, GRU_IN,
                                                 GRU_IN, NCH_GRU, wr, conv_r_b, rfeat);

    // r -> sigmoid(r)*feat
    {
        size_t n = (size_t)Bn * TC * HW;
        gru_rfeat_k<<<(unsigned)((n + 255) / 256), 256>>>(feat);
    }

    // q convolution: [rfeat(64) | hctx ch 64..235]
    conv3x3_mma_k<TC><<<cgrid, 256, CONV_SMEM>>>(rfeat, TC, TC, hctx + (size_t)TC * HW, GRU_IN,
                                                 GRU_IN, NCH_GRU, wq, conv_q_b, qpre);

    // GRU combine -> h_new
    {
        size_t n = (size_t)Bn * TC * HW;
        gru_combine_k<<<(unsigned)((n + 255) / 256), 256>>>(feat, h_new);
    }

    // trunk1: 64 -> 48
    conv3x3_mma_k<HID><<<cgrid, 256, CONV_SMEM>>>(h_new, TC, TC, h_new, TC,
                                                  TC, NCH_T1, wt1, nullptr, ta);
    gn_stats_k<<<Bn * Gg, 256>>>(ta);
    {
        size_t n = (size_t)Bn * HID * HW;
        gn_apply_silu_k<<<(unsigned)((n + 255) / 256), 256>>>(ta, gn1_s, gn1_b, tb);
    }

    // trunk2: 48 -> 48
    conv3x3_mma_k<HID><<<cgrid, 256, CONV_SMEM>>>(tb, HID, HID, tb, HID,
                                                  HID, NCH_T2, wt2, nullptr, ta);
    gn_stats_k<<<Bn * Gg, 256>>>(ta);
    {
        size_t n = (size_t)Bn * HID * HW;
        gn_apply_silu_k<<<(unsigned)((n + 255) / 256), 256>>>(ta, gn2_s, gn2_b, tb);
    }

    // heads
    heads_k<<<(Bn * HW + 255) / 256, 256>>>(tb, d, sx, sy, conf,
                                            head_d_w, head_d_b, head_sx_w, head_sx_b,
                                            head_sy_w, head_sy_b, head_conf_w, head_conf_b,
                                            out);
}

// round 17
// speedup vs baseline: 4.0349x; 2.2229x over previous
#include <cuda_runtime.h>
#include <math.h>
#include <stdint.h>

// ---------------- problem constants ----------------
constexpr int Bn   = 4;
constexpr int FC   = 64;
constexpr int TC   = 64;
constexpr int HID  = 48;
constexpr int HR   = 2;
constexpr int Gg   = 8;
constexpr int Hh   = 128;
constexpr int Wd   = 256;
constexpr int Dd   = 2 * HR + 1;      // 5
constexpr int CG   = FC / Gg;          // 8
constexpr int GRU_IN = TC + 2 * FC + 4 + Gg * Dd;  // 236
constexpr int HW   = Hh * Wd;          // 32768

// output layout: d(4*HW) sx(4*HW) sy(4*HW) h_new(4*64*HW) conf(4*HW)
constexpr size_t O_D    = 0;
constexpr size_t O_SX   = (size_t)Bn * HW;
constexpr size_t O_SY   = 2 * (size_t)Bn * HW;
constexpr size_t O_H    = 3 * (size_t)Bn * HW;
constexpr size_t O_CONF = 3 * (size_t)Bn * HW + (size_t)Bn * TC * HW;

// ---------------- scratch (no allocations allowed) ----------------
__device__ float g_hctx [(size_t)Bn * GRU_IN * HW];
__device__ float g_zpre [(size_t)Bn * TC * HW];
__device__ float g_rfeat[(size_t)Bn * TC * HW];
__device__ float g_qpre [(size_t)Bn * TC * HW];
__device__ float g_ta   [(size_t)Bn * HID * HW];
__device__ float g_tb   [(size_t)Bn * HID * HW];
__device__ float g_stats[Bn * Gg * 2];

// prepacked weights (tf32 bits): [chunk][tap][k=32][n=64]
constexpr int NCH_GRU = (GRU_IN + 31) / 32;   // 8
constexpr int NCH_T1  = (TC + 31) / 32;       // 2
constexpr int NCH_T2  = (HID + 31) / 32;      // 2
__device__ float g_wz [(size_t)NCH_GRU * 9 * 32 * 64];
__device__ float g_wr [(size_t)NCH_GRU * 9 * 32 * 64];
__device__ float g_wq [(size_t)NCH_GRU * 9 * 32 * 64];
__device__ float g_wt1[(size_t)NCH_T1  * 9 * 32 * 64];
__device__ float g_wt2[(size_t)NCH_T2  * 9 * 32 * 64];

// ---------------- helpers ----------------
__device__ __forceinline__ float sigmoidf_(float x) { return 1.f / (1.f + expf(-x)); }
__device__ __forceinline__ float softplusf_(float x) {
    return fmaxf(x, 0.f) + log1pf(expf(-fabsf(x)));
}
__device__ __forceinline__ float f2tf32f(float f) {
    uint32_t o;
    asm("cvt.rna.tf32.f32 %0, %1;" : "=r"(o) : "f"(f));
    return __uint_as_float(o);
}

// ---------------- K1: sampling + cost volume + ctx assembly ----------------
__global__ void build_ctx_k(const float* __restrict__ d, const float* __restrict__ sx,
                            const float* __restrict__ sy, const float* __restrict__ conf,
                            const float* __restrict__ feat, const float* __restrict__ fL,
                            const float* __restrict__ fR) {
    int idx = blockIdx.x * blockDim.x + threadIdx.x;
    if (idx >= Bn * HW) return;
    int b = idx / HW;
    int p = idx - b * HW;
    int w = p & (Wd - 1);

    float d0 = d[(size_t)b * HW + p];

    int i0[Dd], i1[Dd];
    float w1[Dd];
#pragma unroll
    for (int j = 0; j < Dd; j++) {
        float x = (float)w - d0 - (float)(j - HR);
        x = fminf(fmaxf(x, 0.f), (float)(Wd - 1));
        float x0 = floorf(x);
        w1[j] = x - x0;
        i0[j] = (int)x0;
        i1[j] = min(i0[j] + 1, Wd - 1);
    }

    float* hb = g_hctx + (size_t)b * GRU_IN * HW;
    const float* fRrow = fR + (size_t)b * FC * HW + (size_t)(p - w);
    const float* fLp   = fL + (size_t)b * FC * HW + p;
    const float* ftp   = feat + (size_t)b * FC * HW + p;

    float cost[Dd] = {0.f, 0.f, 0.f, 0.f, 0.f};
    for (int c = 0; c < FC; c++) {
        const float* row = fRrow + (size_t)c * HW;
        float fl = fLp[(size_t)c * HW];
        hb[(size_t)c * HW + p]        = ftp[(size_t)c * HW];
        hb[(size_t)(FC + c) * HW + p] = fl;
#pragma unroll
        for (int j = 0; j < Dd; j++) {
            float s = row[i0[j]] * (1.f - w1[j]) + row[i1[j]] * w1[j];
            cost[j] += fl * s;
            if (j == HR) hb[(size_t)(2 * FC + c) * HW + p] = s;
        }
        if ((c & (CG - 1)) == CG - 1) {
            int g = c >> 3;
#pragma unroll
            for (int j = 0; j < Dd; j++) {
                hb[(size_t)(3 * FC + 4 + g * Dd + j) * HW + p] = cost[j] * (1.f / (float)CG);
                cost[j] = 0.f;
            }
        }
    }
    hb[(size_t)(3 * FC + 0) * HW + p] = d0;
    hb[(size_t)(3 * FC + 1) * HW + p] = sx[(size_t)b * HW + p];
    hb[(size_t)(3 * FC + 2) * HW + p] = sy[(size_t)b * HW + p];
    hb[(size_t)(3 * FC + 3) * HW + p] = conf[(size_t)b * HW + p];
}

// ---------------- weight prepack (tf32) ----------------
__global__ void prepack_mma_k(const float* __restrict__ w, float* __restrict__ dst,
                              int c_total, int cout, int nchunks) {
    int total = nchunks * 9 * 32 * 64;
    int i = blockIdx.x * blockDim.x + threadIdx.x;
    if (i >= total) return;
    int n   = i & 63;
    int k   = (i >> 6) & 31;
    int tap = (i >> 11) % 9;
    int ch  = i / (2048 * 9);
    int c = ch * 32 + k;
    float v = (c < c_total && n < cout) ? w[((size_t)n * c_total + c) * 9 + tap] : 0.f;
    dst[i] = f2tf32f(v);
}

// ---------------- mma.sync tf32 implicit-GEMM 3x3 conv ----------------
// CTA = one (b,y) image row: M=256 px, N=64 (COUT padded).
// 16 warps: warpM = wid&7 (32 px), warpN = wid>>3 (32 ch).
// smem A: [32 ch][264] with xi = gx + 4 (4-float halo both sides, float4 aligned).
// smem B: [3 taps][32 k][72].
constexpr int SA_PITCH = 264;   // %32 == 8 -> conflict-free frag loads
constexpr int SB_PITCH = 72;    // %32 == 8
constexpr int CONV_SMEM = (32 * SA_PITCH + 3 * 32 * SB_PITCH) * 4;  // 61440 B
constexpr int CT = 512;

template <int COUT>
__global__ __launch_bounds__(CT)
void conv3x3_mma_k(const float* __restrict__ Ahead, int head_bstride, int c_head,
                   const float* __restrict__ Arest, int rest_bstride,
                   int c_total, int nchunks,
                   const float* __restrict__ wpack, const float* __restrict__ bias,
                   float* __restrict__ out) {
    extern __shared__ float smem[];
    float* sA = smem;                       // [32][SA_PITCH]
    float* sB = smem + 32 * SA_PITCH;       // [3][32][SB_PITCH]

    const int tid  = threadIdx.x;
    const int wid  = tid >> 5;
    const int lane = tid & 31;
    const int gid  = lane >> 2;   // 0..7
    const int tig  = lane & 3;    // 0..3
    const int warpM = wid & 7;    // 0..7  (32 px)
    const int warpN = wid >> 3;   // 0..1  (32 ch)

    const int y = blockIdx.x;
    const int b = blockIdx.y;

    const float* pa_b = Ahead + (size_t)b * head_bstride * HW;
    const float* pr_b = Arest + (size_t)b * rest_bstride * HW;

    float acc[2][4][4];
#pragma unroll
    for (int mf = 0; mf < 2; mf++)
#pragma unroll
        for (int nf = 0; nf < 4; nf++)
#pragma unroll
            for (int r = 0; r < 4; r++) acc[mf][nf][r] = 0.f;

    for (int chunk = 0; chunk < nchunks; ++chunk) {
        for (int dy = 0; dy < 3; ++dy) {
            const int yy = y + dy - 1;
            __syncthreads();   // previous iteration's reads done

            // ---- fill A: flattened float4 loop, xi = gx + 4 ----
            {
                const bool rowok = (yy >= 0) && (yy < Hh);
                for (int i = tid; i < 32 * 66; i += CT) {
                    const int c   = i / 66;
                    const int v4i = i - c * 66;     // float4 index within row
                    const int cg  = chunk * 32 + c;
                    float4 val = make_float4(0.f, 0.f, 0.f, 0.f);
                    if (rowok && cg < c_total && v4i >= 1 && v4i <= 64) {
                        const float* src = (cg < c_head ? pa_b + (size_t)cg * HW
                                                        : pr_b + (size_t)(cg - c_head) * HW)
                                           + (size_t)yy * Wd + (v4i - 1) * 4;
                        float4 t = *reinterpret_cast<const float4*>(src);
                        val.x = f2tf32f(t.x); val.y = f2tf32f(t.y);
                        val.z = f2tf32f(t.z); val.w = f2tf32f(t.w);
                    }
                    *reinterpret_cast<float4*>(sA + c * SA_PITCH + v4i * 4) = val;
                }
            }
            // ---- fill B: taps dy*3+0..2, each [32][64] -> pitch 72 ----
            {
                const float* wsrc = wpack + ((size_t)chunk * 9 + dy * 3) * (32 * 64);
                for (int i = tid; i < 3 * 32 * 64; i += CT) {
                    int t = i >> 11;
                    int k = (i >> 6) & 31;
                    int n = i & 63;
                    sB[(t * 32 + k) * SB_PITCH + n] = wsrc[i];
                }
            }
            __syncthreads();

            // ---- compute: 3 dx taps x 4 ksteps ----
            for (int dx = 0; dx < 3; ++dx) {
                const float* sBt = sB + dx * 32 * SB_PITCH;
                // output px m reads gx = m + dx - 1 -> xi = m + dx + 3
                const int x0 = warpM * 32 + gid + dx + 3;
#pragma unroll
                for (int ks = 0; ks < 4; ++ks) {
                    const int k0 = ks * 8 + tig;
                    uint32_t bf[4][2];
#pragma unroll
                    for (int nf = 0; nf < 4; ++nf) {
                        const int n0 = warpN * 32 + nf * 8 + gid;
                        bf[nf][0] = __float_as_uint(sBt[k0 * SB_PITCH + n0]);
                        bf[nf][1] = __float_as_uint(sBt[(k0 + 4) * SB_PITCH + n0]);
                    }
                    uint32_t af[2][4];
#pragma unroll
                    for (int mf = 0; mf < 2; ++mf) {
                        const int xm = x0 + mf * 16;
                        af[mf][0] = __float_as_uint(sA[k0 * SA_PITCH + xm]);
                        af[mf][1] = __float_as_uint(sA[k0 * SA_PITCH + xm + 8]);
                        af[mf][2] = __float_as_uint(sA[(k0 + 4) * SA_PITCH + xm]);
                        af[mf][3] = __float_as_uint(sA[(k0 + 4) * SA_PITCH + xm + 8]);
                    }
#pragma unroll
                    for (int mf = 0; mf < 2; ++mf)
#pragma unroll
                        for (int nf = 0; nf < 4; ++nf)
                            asm volatile(
                                "mma.sync.aligned.m16n8k8.row.col.f32.tf32.tf32.f32 "
                                "{%0,%1,%2,%3}, {%4,%5,%6,%7}, {%8,%9}, {%0,%1,%2,%3};"
                                : "+f"(acc[mf][nf][0]), "+f"(acc[mf][nf][1]),
                                  "+f"(acc[mf][nf][2]), "+f"(acc[mf][nf][3])
                                : "r"(af[mf][0]), "r"(af[mf][1]),
                                  "r"(af[mf][2]), "r"(af[mf][3]),
                                  "r"(bf[nf][0]), "r"(bf[nf][1]));
                }
            }
        }
    }

    // ---- epilogue ----
    float* ob = out + (size_t)b * COUT * HW + (size_t)y * Wd;
#pragma unroll
    for (int mf = 0; mf < 2; ++mf) {
        const int m0 = warpM * 32 + mf * 16 + gid;
#pragma unroll
        for (int nf = 0; nf < 4; ++nf) {
            const int n0 = warpN * 32 + nf * 8 + 2 * tig;
#pragma unroll
            for (int r = 0; r < 4; ++r) {
                const int n = n0 + (r & 1);
                const int m = m0 + ((r >> 1) ? 8 : 0);
                if (n < COUT) {
                    float v = acc[mf][nf][r];
                    if (bias) v += bias[n];
                    ob[(size_t)n * HW + m] = v;
                }
            }
        }
    }
}

// ---------------- GRU elementwise ----------------
__global__ void gru_rfeat_k(const float* __restrict__ feat) {
    size_t i = (size_t)blockIdx.x * blockDim.x + threadIdx.x;
    if (i >= (size_t)Bn * TC * HW) return;
    g_rfeat[i] = sigmoidf_(g_rfeat[i]) * feat[i];
}

__global__ void gru_combine_k(const float* __restrict__ feat, float* __restrict__ out_h) {
    size_t i = (size_t)blockIdx.x * blockDim.x + threadIdx.x;
    if (i >= (size_t)Bn * TC * HW) return;
    float z = sigmoidf_(g_zpre[i]);
    float q = tanhf(g_qpre[i]);
    out_h[i] = (1.f - z) * feat[i] + z * q;
}

// ---------------- group norm ----------------
__global__ void gn_stats_k(const float* __restrict__ x) {
    const int bg = blockIdx.x;
    const int b = bg >> 3, g = bg & 7;
    const float* base = x + ((size_t)b * HID + g * (HID / Gg)) * HW;
    const int n = (HID / Gg) * HW;
    float s = 0.f, s2 = 0.f;
    for (int i = threadIdx.x; i < n; i += blockDim.x) {
        float v = base[i];
        s += v; s2 += v * v;
    }
    __shared__ float sh[512];
    sh[threadIdx.x] = s;
    sh[256 + threadIdx.x] = s2;
    __syncthreads();
    for (int o = 128; o > 0; o >>= 1) {
        if (threadIdx.x < o) {
            sh[threadIdx.x] += sh[threadIdx.x + o];
            sh[256 + threadIdx.x] += sh[256 + threadIdx.x + o];
        }
        __syncthreads();
    }
    if (threadIdx.x == 0) {
        float m = sh[0] / (float)n;
        float var = sh[256] / (float)n - m * m;
        g_stats[bg * 2]     = m;
        g_stats[bg * 2 + 1] = rsqrtf(var + 1e-5f);
    }
}

__global__ void gn_apply_silu_k(const float* __restrict__ x,
                                const float* __restrict__ scale, const float* __restrict__ bias,
                                float* __restrict__ y) {
    size_t i = (size_t)blockIdx.x * blockDim.x + threadIdx.x;
    if (i >= (size_t)Bn * HID * HW) return;
    int c = (int)((i / HW) % HID);
    int b = (int)(i / ((size_t)HID * HW));
    int g = c / (HID / Gg);
    float m = g_stats[(b * Gg + g) * 2];
    float r = g_stats[(b * Gg + g) * 2 + 1];
    float v = (x[i] - m) * r * scale[c] + bias[c];
    y[i] = v * sigmoidf_(v);
}

// ---------------- heads ----------------
__global__ void heads_k(const float* __restrict__ t,
                        const float* __restrict__ d, const float* __restrict__ sx,
                        const float* __restrict__ sy, const float* __restrict__ conf,
                        const float* __restrict__ wd, const float* __restrict__ bd,
                        const float* __restrict__ wsx, const float* __restrict__ bsx,
                        const float* __restrict__ wsy, const float* __restrict__ bsy,
                        const float* __restrict__ wc, const float* __restrict__ bc,
                        float* __restrict__ out) {
    int idx = blockIdx.x * blockDim.x + threadIdx.x;
    if (idx >= Bn * HW) return;
    int b = idx / HW;
    int p = idx - b * HW;
    const float* tb = t + (size_t)b * HID * HW + p;
    float ad = 0.f, asx = 0.f, asy = 0.f, ac = 0.f;
#pragma unroll
    for (int c = 0; c < HID; c++) {
        float v = tb[(size_t)c * HW];
        ad  += v * __ldg(&wd[c]);
        asx += v * __ldg(&wsx[c]);
        asy += v * __ldg(&wsy[c]);
        ac  += v * __ldg(&wc[c]);
    }
    float dv = d[idx];
    out[O_D + idx]    = softplusf_(ad + bd[0] + dv);
    out[O_SX + idx]   = sx[idx] + (asx + bsx[0]) * 0.1f;
    out[O_SY + idx]   = sy[idx] + (asy + bsy[0]) * 0.1f;
    out[O_CONF + idx] = sigmoidf_(ac + bc[0] + 2.f * conf[idx] - 1.f);
}

// ---------------- launch ----------------
extern "C" void kernel_launch(void* const* d_in, const int* in_sizes, int n_in,
                              void* d_out, int out_size) {
    const float* d      = (const float*)d_in[0];
    const float* sx     = (const float*)d_in[1];
    const float* sy     = (const float*)d_in[2];
    const float* conf   = (const float*)d_in[3];
    const float* feat   = (const float*)d_in[4];
    const float* fL     = (const float*)d_in[5];
    const float* fR     = (const float*)d_in[6];
    const float* conv_z_w = (const float*)d_in[7];
    const float* conv_z_b = (const float*)d_in[8];
    const float* conv_r_w = (const float*)d_in[9];
    const float* conv_r_b = (const float*)d_in[10];
    const float* conv_q_w = (const float*)d_in[11];
    const float* conv_q_b = (const float*)d_in[12];
    const float* trunk1_w = (const float*)d_in[13];
    const float* gn1_s    = (const float*)d_in[14];
    const float* gn1_b    = (const float*)d_in[15];
    const float* trunk2_w = (const float*)d_in[16];
    const float* gn2_s    = (const float*)d_in[17];
    const float* gn2_b    = (const float*)d_in[18];
    const float* head_d_w    = (const float*)d_in[19];
    const float* head_d_b    = (const float*)d_in[20];
    const float* head_sx_w   = (const float*)d_in[21];
    const float* head_sx_b   = (const float*)d_in[22];
    const float* head_sy_w   = (const float*)d_in[23];
    const float* head_sy_b   = (const float*)d_in[24];
    const float* head_conf_w = (const float*)d_in[25];
    const float* head_conf_b = (const float*)d_in[26];

    float* out = (float*)d_out;

    float *hctx, *zpre, *rfeat, *qpre, *ta, *tb;
    float *wz, *wr, *wq, *wt1, *wt2;
    cudaGetSymbolAddress((void**)&hctx,  g_hctx);
    cudaGetSymbolAddress((void**)&zpre,  g_zpre);
    cudaGetSymbolAddress((void**)&rfeat, g_rfeat);
    cudaGetSymbolAddress((void**)&qpre,  g_qpre);
    cudaGetSymbolAddress((void**)&ta,    g_ta);
    cudaGetSymbolAddress((void**)&tb,    g_tb);
    cudaGetSymbolAddress((void**)&wz,    g_wz);
    cudaGetSymbolAddress((void**)&wr,    g_wr);
    cudaGetSymbolAddress((void**)&wq,    g_wq);
    cudaGetSymbolAddress((void**)&wt1,   g_wt1);
    cudaGetSymbolAddress((void**)&wt2,   g_wt2);

    float* h_new = out + O_H;

    cudaFuncSetAttribute(conv3x3_mma_k<TC>,  cudaFuncAttributeMaxDynamicSharedMemorySize, CONV_SMEM);
    cudaFuncSetAttribute(conv3x3_mma_k<HID>, cudaFuncAttributeMaxDynamicSharedMemorySize, CONV_SMEM);

    dim3 cgrid(Hh, Bn);
    int nG = NCH_GRU * 9 * 32 * 64;

    // launch order arranged so conv_z is the 4th launch (ncu capture slot)
    prepack_mma_k<<<(nG + 255) / 256, 256>>>(conv_z_w, wz, GRU_IN, TC, NCH_GRU);     // 1
    build_ctx_k<<<(Bn * HW + 255) / 256, 256>>>(d, sx, sy, conf, feat, fL, fR);      // 2
    prepack_mma_k<<<(nG + 255) / 256, 256>>>(conv_r_w, wr, GRU_IN, TC, NCH_GRU);     // 3
    conv3x3_mma_k<TC><<<cgrid, CT, CONV_SMEM>>>(hctx, GRU_IN, GRU_IN, hctx, GRU_IN,  // 4
                                                GRU_IN, NCH_GRU, wz, conv_z_b, zpre);
    prepack_mma_k<<<(nG + 255) / 256, 256>>>(conv_q_w, wq, GRU_IN, TC, NCH_GRU);     // 5
    conv3x3_mma_k<TC><<<cgrid, CT, CONV_SMEM>>>(hctx, GRU_IN, GRU_IN, hctx, GRU_IN,  // 6
                                                GRU_IN, NCH_GRU, wr, conv_r_b, rfeat);
    {
        size_t n = (size_t)Bn * TC * HW;
        gru_rfeat_k<<<(unsigned)((n + 255) / 256), 256>>>(feat);
    }
    conv3x3_mma_k<TC><<<cgrid, CT, CONV_SMEM>>>(rfeat, TC, TC, hctx + (size_t)TC * HW, GRU_IN,
                                                GRU_IN, NCH_GRU, wq, conv_q_b, qpre);
    {
        size_t n = (size_t)Bn * TC * HW;
        gru_combine_k<<<(unsigned)((n + 255) / 256), 256>>>(feat, h_new);
    }

    // trunk1: 64 -> 48
    {
        int n1 = NCH_T1 * 9 * 32 * 64;
        prepack_mma_k<<<(n1 + 255) / 256, 256>>>(trunk1_w, wt1, TC, HID, NCH_T1);
    }
    conv3x3_mma_k<HID><<<cgrid, CT, CONV_SMEM>>>(h_new, TC, TC, h_new, TC,
                                                 TC, NCH_T1, wt1, nullptr, ta);
    gn_stats_k<<<Bn * Gg, 256>>>(ta);
    {
        size_t n = (size_t)Bn * HID * HW;
        gn_apply_silu_k<<<(unsigned)((n + 255) / 256), 256>>>(ta, gn1_s, gn1_b, tb);
    }

    // trunk2: 48 -> 48
    {
        int n2 = NCH_T2 * 9 * 32 * 64;
        prepack_mma_k<<<(n2 + 255) / 256, 256>>>(trunk2_w, wt2, HID, HID, NCH_T2);
    }
    conv3x3_mma_k<HID><<<cgrid, CT, CONV_SMEM>>>(tb, HID, HID, tb, HID,
                                                 HID, NCH_T2, wt2, nullptr, ta);
    gn_stats_k<<<Bn * Gg, 256>>>(ta);
    {
        size_t n = (size_t)Bn * HID * HW;
        gn_apply_silu_k<<<(unsigned)((n + 255) / 256), 256>>>(ta, gn2_s, gn2_b, tb);
    }

    // heads
    heads_k<<<(Bn * HW + 255) / 256, 256>>>(tb, d, sx, sy, conf,
                                            head_d_w, head_d_b, head_sx_w, head_sx_b,
                                            head_sy_w, head_sy_b, head_conf_w, head_conf_b,
                                            out);
}